// round 12
// baseline (speedup 1.0000x reference)
#include <cuda_runtime.h>
#include <cuda_bf16.h>
#include <math.h>

// Problem constants
#define T_TOK 4096
#define H_DIM 1024
#define I_DIM 4096
#define E_EXP 8
#define K_TOP 2
#define P_PAIR (T_TOK * K_TOP)
#define HP (H_DIM / 2)   // k-pairs along H
#define IP (I_DIM / 2)   // k-pairs along I

// ---------------- scratch (static device globals; no runtime alloc) ----------
// bf16x3 split storage: one uint2 per k-PAIR of fp32 elements:
//   .x = bf16x2{hi(k_even), hi(k_odd)}
//   .y = bf16x2{lo(k_even), lo(k_odd)}   (residuals)
__device__ uint2 g_xs [(size_t)T_TOK * HP];
__device__ uint2 g_wgs[(size_t)E_EXP * HP * I_DIM];
__device__ uint2 g_wus[(size_t)E_EXP * HP * I_DIM];
__device__ uint2 g_wds[(size_t)E_EXP * IP * H_DIM];
__device__ uint2 g_hdns[(size_t)P_PAIR * IP];
__device__ float g_pairout[(size_t)P_PAIR * H_DIM];
__device__ int   g_perm[P_PAIR];
__device__ float g_pairw[P_PAIR];
__device__ int   g_pos[P_PAIR];
__device__ int   g_tki[T_TOK * K_TOP];
__device__ float g_tkw[T_TOK * K_TOP];
__device__ int   g_counts[E_EXP];
__device__ int   g_offsets[E_EXP];
__device__ int   g_cursor[E_EXP];
__device__ float g_load[E_EXP];

// ---------------- bf16 split + mma helpers -----------------------------------
__device__ __forceinline__ uint2 split_pair(float e0, float e1) {
    __nv_bfloat16 h0 = __float2bfloat16_rn(e0);
    __nv_bfloat16 h1 = __float2bfloat16_rn(e1);
    float r0 = e0 - __bfloat162float(h0);
    float r1 = e1 - __bfloat162float(h1);
    __nv_bfloat16 l0 = __float2bfloat16_rn(r0);
    __nv_bfloat16 l1 = __float2bfloat16_rn(r1);
    uint2 o;
    o.x = (unsigned)__bfloat16_as_ushort(h0) | ((unsigned)__bfloat16_as_ushort(h1) << 16);
    o.y = (unsigned)__bfloat16_as_ushort(l0) | ((unsigned)__bfloat16_as_ushort(l1) << 16);
    return o;
}
__device__ __forceinline__ void mma16(float* c, unsigned a0, unsigned a1,
                                      unsigned a2, unsigned a3,
                                      unsigned b0, unsigned b1) {
    asm volatile(
        "mma.sync.aligned.m16n8k16.row.col.f32.bf16.bf16.f32 "
        "{%0,%1,%2,%3}, {%4,%5,%6,%7}, {%8,%9}, {%0,%1,%2,%3};"
        : "+f"(c[0]), "+f"(c[1]), "+f"(c[2]), "+f"(c[3])
        : "r"(a0), "r"(a1), "r"(a2), "r"(a3), "r"(b0), "r"(b1));
}
__device__ __forceinline__ void mma3(float* c, const uint2 a[4], uint2 b0, uint2 b1) {
    mma16(c, a[0].x, a[1].x, a[2].x, a[3].x, b0.x, b1.x);
    mma16(c, a[0].y, a[1].y, a[2].y, a[3].y, b0.x, b1.x);
    mma16(c, a[0].x, a[1].x, a[2].x, a[3].x, b0.y, b1.y);
}
__device__ __forceinline__ void cp16(unsigned dst, const void* src) {
    asm volatile("cp.async.cg.shared.global [%0], [%1], 16;" :: "r"(dst), "l"(src));
}
#define CP_COMMIT() asm volatile("cp.async.commit_group;")
#define CP_WAIT(n)  asm volatile("cp.async.wait_group %0;" :: "n"(n))

// ---------------- small kernels ----------------------------------------------
__global__ void zero_kernel() {
    int i = threadIdx.x;
    if (i < E_EXP) { g_counts[i] = 0; g_load[i] = 0.f; }
}

__global__ void router_kernel(const float* __restrict__ x,
                              const float* __restrict__ gw) {
    int t = blockIdx.x;
    int w = threadIdx.x >> 5, lane = threadIdx.x & 31;
    __shared__ float logits[E_EXP];
    const float* xr = x + (size_t)t * H_DIM;
    float s = 0.f;
    for (int h = lane; h < H_DIM; h += 32)
        s += xr[h] * gw[h * E_EXP + w];
    #pragma unroll
    for (int o = 16; o; o >>= 1) s += __shfl_xor_sync(0xffffffffu, s, o);
    if (lane == 0) logits[w] = s;
    __syncthreads();
    if (threadIdx.x == 0) {
        float mx = logits[0];
        #pragma unroll
        for (int e = 1; e < E_EXP; e++) mx = fmaxf(mx, logits[e]);
        float p[E_EXP], den = 0.f;
        #pragma unroll
        for (int e = 0; e < E_EXP; e++) { p[e] = expf(logits[e] - mx); den += p[e]; }
        #pragma unroll
        for (int e = 0; e < E_EXP; e++) p[e] /= den;
        int i0 = 0;
        #pragma unroll
        for (int e = 1; e < E_EXP; e++) if (p[e] > p[i0]) i0 = e;
        int i1 = -1;
        #pragma unroll
        for (int e = 0; e < E_EXP; e++) {
            if (e == i0) continue;
            if (i1 < 0 || p[e] > p[i1]) i1 = e;
        }
        float w0 = p[i0], w1 = p[i1], sm = w0 + w1;
        g_tki[t * 2 + 0] = i0; g_tki[t * 2 + 1] = i1;
        g_tkw[t * 2 + 0] = w0 / sm; g_tkw[t * 2 + 1] = w1 / sm;
        atomicAdd(&g_counts[i0], 1); atomicAdd(&g_counts[i1], 1);
        atomicAdd(&g_load[i0], w0);  atomicAdd(&g_load[i1], w1);
    }
}

__global__ void finalize_router(float* out_aux, int write_aux) {
    if (threadIdx.x == 0) {
        int off = 0;
        for (int e = 0; e < E_EXP; e++) {
            g_offsets[e] = off; g_cursor[e] = off; off += g_counts[e];
        }
        if (write_aux) {
            float aux = 0.f;
            for (int e = 0; e < E_EXP; e++) {
                float Pe = g_load[e] / (float)T_TOK;
                float Pt = (float)g_counts[e] / (float)(T_TOK * K_TOP);
                aux += Pe * Pt;
            }
            *out_aux = aux * (float)E_EXP * 0.001f;
        }
    }
}

__global__ void scatter_kernel() {
    int t = blockIdx.x * blockDim.x + threadIdx.x;
    if (t >= T_TOK) return;
    #pragma unroll
    for (int k = 0; k < K_TOP; k++) {
        int e = g_tki[t * 2 + k];
        int p = atomicAdd(&g_cursor[e], 1);
        g_perm[p] = t;
        g_pairw[p] = g_tkw[t * 2 + k];
        g_pos[t * 2 + k] = p;
    }
}

// ---------------- preprocessing ----------------------------------------------
__global__ void split_x_kernel(const float* __restrict__ src,
                               uint2* __restrict__ dst, long n4) {
    long stride = (long)gridDim.x * blockDim.x;
    for (long i = (long)blockIdx.x * blockDim.x + threadIdx.x; i < n4; i += stride) {
        float4 v = ((const float4*)src)[i];
        uint2 p0 = split_pair(v.x, v.y);
        uint2 p1 = split_pair(v.z, v.w);
        uint4 o; o.x = p0.x; o.y = p0.y; o.z = p1.x; o.w = p1.y;
        ((uint4*)dst)[i] = o;
    }
}

__global__ void split_w_kernel(const float* __restrict__ src,
                               uint2* __restrict__ dst, long Rp, int C) {
    long total = Rp * (long)(C / 4);
    long stride = (long)gridDim.x * blockDim.x;
    int c4 = C / 4;
    for (long i = (long)blockIdx.x * blockDim.x + threadIdx.x; i < total; i += stride) {
        long kp = i / c4;
        int  n4 = (int)(i % c4) * 4;
        const float* r0 = src + (size_t)(2 * kp) * C + n4;
        float4 a = *(const float4*)r0;
        float4 b = *(const float4*)(r0 + C);
        uint2 p0 = split_pair(a.x, b.x);
        uint2 p1 = split_pair(a.y, b.y);
        uint2 p2 = split_pair(a.z, b.z);
        uint2 p3 = split_pair(a.w, b.w);
        uint2* dp = dst + (size_t)kp * C + n4;
        uint4 o0; o0.x = p0.x; o0.y = p0.y; o0.z = p1.x; o0.w = p1.y;
        uint4 o1; o1.x = p2.x; o1.y = p2.y; o1.z = p3.x; o1.w = p3.y;
        ((uint4*)dp)[0] = o0;
        ((uint4*)dp)[1] = o1;
    }
}

// ---------------- GEMM1: hdn = silu(X@wg[e]) * (X@wu[e]) ---------------------
// Block 128M x 64N, 8 warps 4mx2n, warp tile 32x32 for G and U.
// 4-stage cp.async ring, k16 per stage (8 pairs). One sync/iter.
#define F1_AS 1536          // 128*12 uint2
#define F1_BS 544           // 8*68 uint2
#define F1_STG (F1_AS + 2 * F1_BS)   // 2624 uint2 = 20992 B per stage
__global__ void __launch_bounds__(256) ffn1_kernel() {
    extern __shared__ __align__(16) uint2 dsm[];
    __shared__ int perm_s[128];

    const int e = blockIdx.z;
    const int cnt = g_counts[e];
    const int m0 = blockIdx.x * 128;
    if (m0 >= cnt) return;
    const int beg = g_offsets[e];
    const int n0 = blockIdx.y * 64;
    const int tid = threadIdx.x;

    if (tid < 128) {
        int r = m0 + tid;
        perm_s[tid] = g_perm[beg + (r < cnt ? r : cnt - 1)];
    }
    __syncthreads();

    const int ar  = tid >> 1;
    const int apb = (tid & 1) * 4;
    const uint2* axr = g_xs + (size_t)perm_s[ar] * HP + apb;
    const int bkp = tid >> 5;
    const int bn  = (tid & 31) * 2;
    const size_t eoffB = (size_t)e * HP * I_DIM;
    const uint2* bgp = g_wgs + eoffB + (size_t)bkp * I_DIM + n0 + bn;
    const uint2* bup = g_wus + eoffB + (size_t)bkp * I_DIM + n0 + bn;

    const unsigned sm0 = (unsigned)__cvta_generic_to_shared(dsm);
    const unsigned a_sm = sm0 + (unsigned)(ar * 12 + apb) * 8;
    const unsigned g_sm = sm0 + (unsigned)(F1_AS + bkp * 68 + bn) * 8;
    const unsigned u_sm = sm0 + (unsigned)(F1_AS + F1_BS + bkp * 68 + bn) * 8;
    const unsigned STGB = F1_STG * 8;

    const int w = tid >> 5, lane = tid & 31;
    const int wm = (w >> 1) * 32, wn = (w & 1) * 32;
    const int fr = lane >> 2, fc = lane & 3;

    float accG[2][4][4] = {}, accU[2][4][4] = {};

    const int KT = HP / 8;  // 64
    // prologue: fill stages 0..2
    #pragma unroll
    for (int s = 0; s < 3; s++) {
        const uint2* a2 = axr + s * 8;
        cp16(a_sm + s * STGB, a2); cp16(a_sm + s * STGB + 16, a2 + 2);
        cp16(g_sm + s * STGB, bgp + (size_t)s * 8 * I_DIM);
        cp16(u_sm + s * STGB, bup + (size_t)s * 8 * I_DIM);
        CP_COMMIT();
    }

    for (int kt = 0; kt < KT; kt++) {
        CP_WAIT(2);          // stage kt landed
        __syncthreads();     // visible to all; all warps done with stage kt-1
        const int pf = kt + 3;
        if (pf < KT) {
            const unsigned so = (unsigned)(pf & 3) * STGB;
            const uint2* a2 = axr + pf * 8;
            cp16(a_sm + so, a2); cp16(a_sm + so + 16, a2 + 2);
            cp16(g_sm + so, bgp + (size_t)pf * 8 * I_DIM);
            cp16(u_sm + so, bup + (size_t)pf * 8 * I_DIM);
        }
        CP_COMMIT();         // keep group count aligned (empty near tail)

        const uint2* A  = dsm + (kt & 3) * F1_STG;
        const uint2* BG = A + F1_AS;
        const uint2* BU = BG + F1_BS;
        uint2 a[2][4];
        #pragma unroll
        for (int mi = 0; mi < 2; mi++) {
            int mr = wm + mi * 16 + fr;
            a[mi][0] = A[mr * 12 + fc];
            a[mi][1] = A[(mr + 8) * 12 + fc];
            a[mi][2] = A[mr * 12 + fc + 4];
            a[mi][3] = A[(mr + 8) * 12 + fc + 4];
        }
        #pragma unroll
        for (int nj = 0; nj < 4; nj++) {
            int nb = wn + nj * 8 + fr;
            uint2 b0 = BG[fc * 68 + nb], b1 = BG[(fc + 4) * 68 + nb];
            mma3(accG[0][nj], a[0], b0, b1);
            mma3(accG[1][nj], a[1], b0, b1);
            b0 = BU[fc * 68 + nb]; b1 = BU[(fc + 4) * 68 + nb];
            mma3(accU[0][nj], a[0], b0, b1);
            mma3(accU[1][nj], a[1], b0, b1);
        }
    }

    #pragma unroll
    for (int mi = 0; mi < 2; mi++) {
        #pragma unroll
        for (int nj = 0; nj < 4; nj++) {
            int row = m0 + wm + mi * 16 + fr;
            int pr  = (n0 + wn + nj * 8 + 2 * fc) >> 1;
            if (row < cnt) {
                float g0 = accG[mi][nj][0], g1 = accG[mi][nj][1];
                float u0 = accU[mi][nj][0], u1 = accU[mi][nj][1];
                float h0 = g0 / (1.f + expf(-g0)) * u0;
                float h1 = g1 / (1.f + expf(-g1)) * u1;
                g_hdns[(size_t)(beg + row) * IP + pr] = split_pair(h0, h1);
            }
            if (row + 8 < cnt) {
                float g0 = accG[mi][nj][2], g1 = accG[mi][nj][3];
                float u0 = accU[mi][nj][2], u1 = accU[mi][nj][3];
                float h0 = g0 / (1.f + expf(-g0)) * u0;
                float h1 = g1 / (1.f + expf(-g1)) * u1;
                g_hdns[(size_t)(beg + row + 8) * IP + pr] = split_pair(h0, h1);
            }
        }
    }
}

// ---------------- GEMM2: pairout = (hdn @ wd[e]) * pairw ---------------------
// Block 128M x 128N, 8 warps 4mx2n, warp tile 32x64. 4-stage ring.
#define F2_AS 1536
#define F2_BS 1056          // 8*132 uint2
#define F2_STG (F2_AS + F2_BS)    // 2592 uint2 = 20736 B
__global__ void __launch_bounds__(256) ffn2_kernel() {
    extern __shared__ __align__(16) uint2 dsm2[];

    const int e = blockIdx.z;
    const int cnt = g_counts[e];
    const int m0 = blockIdx.x * 128;
    if (m0 >= cnt) return;
    const int beg = g_offsets[e];
    const int n0 = blockIdx.y * 128;
    const int tid = threadIdx.x;

    const int ar  = tid >> 1;
    const int apb = (tid & 1) * 4;
    int rr = m0 + ar; if (rr >= cnt) rr = cnt - 1;
    const uint2* axr = g_hdns + (size_t)(beg + rr) * IP + apb;
    const int bkp = tid >> 5;
    const int bn4 = (tid & 31) * 4;
    const uint2* bp = g_wds + ((size_t)e * IP + bkp) * H_DIM + n0 + bn4;

    const unsigned sm0 = (unsigned)__cvta_generic_to_shared(dsm2);
    const unsigned a_sm = sm0 + (unsigned)(ar * 12 + apb) * 8;
    const unsigned b_sm = sm0 + (unsigned)(F2_AS + bkp * 132 + bn4) * 8;
    const unsigned STGB = F2_STG * 8;

    const int w = tid >> 5, lane = tid & 31;
    const int wm = (w >> 1) * 32, wn = (w & 1) * 64;
    const int fr = lane >> 2, fc = lane & 3;

    float acc[2][8][4] = {};

    const int KT = IP / 8;  // 256
    #pragma unroll
    for (int s = 0; s < 3; s++) {
        const uint2* a2 = axr + s * 8;
        const uint2* b2 = bp + (size_t)s * 8 * H_DIM;
        cp16(a_sm + s * STGB, a2); cp16(a_sm + s * STGB + 16, a2 + 2);
        cp16(b_sm + s * STGB, b2); cp16(b_sm + s * STGB + 16, b2 + 2);
        CP_COMMIT();
    }

    for (int kt = 0; kt < KT; kt++) {
        CP_WAIT(2);
        __syncthreads();
        const int pf = kt + 3;
        if (pf < KT) {
            const unsigned so = (unsigned)(pf & 3) * STGB;
            const uint2* a2 = axr + pf * 8;
            const uint2* b2 = bp + (size_t)pf * 8 * H_DIM;
            cp16(a_sm + so, a2); cp16(a_sm + so + 16, a2 + 2);
            cp16(b_sm + so, b2); cp16(b_sm + so + 16, b2 + 2);
        }
        CP_COMMIT();

        const uint2* A = dsm2 + (kt & 3) * F2_STG;
        const uint2* B = A + F2_AS;
        uint2 a[2][4];
        #pragma unroll
        for (int mi = 0; mi < 2; mi++) {
            int mr = wm + mi * 16 + fr;
            a[mi][0] = A[mr * 12 + fc];
            a[mi][1] = A[(mr + 8) * 12 + fc];
            a[mi][2] = A[mr * 12 + fc + 4];
            a[mi][3] = A[(mr + 8) * 12 + fc + 4];
        }
        #pragma unroll
        for (int nj = 0; nj < 8; nj++) {
            int nb = wn + nj * 8 + fr;
            uint2 b0 = B[fc * 132 + nb], b1 = B[(fc + 4) * 132 + nb];
            mma3(acc[0][nj], a[0], b0, b1);
            mma3(acc[1][nj], a[1], b0, b1);
        }
    }

    #pragma unroll
    for (int mi = 0; mi < 2; mi++) {
        int row = m0 + wm + mi * 16 + fr;
        float pw0 = (row < cnt)     ? g_pairw[beg + row]     : 0.f;
        float pw8 = (row + 8 < cnt) ? g_pairw[beg + row + 8] : 0.f;
        #pragma unroll
        for (int nj = 0; nj < 8; nj++) {
            int col = n0 + wn + nj * 8 + 2 * fc;
            if (row < cnt) {
                float2 v = { acc[mi][nj][0] * pw0, acc[mi][nj][1] * pw0 };
                *(float2*)&g_pairout[(size_t)(beg + row) * H_DIM + col] = v;
            }
            if (row + 8 < cnt) {
                float2 v = { acc[mi][nj][2] * pw8, acc[mi][nj][3] * pw8 };
                *(float2*)&g_pairout[(size_t)(beg + row + 8) * H_DIM + col] = v;
            }
        }
    }
}

// ---------------- combine ------------------------------------------------------
__global__ void combine_kernel(float* __restrict__ out) {
    int idx = blockIdx.x * blockDim.x + threadIdx.x;
    if (idx >= T_TOK * H_DIM) return;
    int t = idx >> 10;
    int h = idx & (H_DIM - 1);
    int p0 = g_pos[t * 2 + 0], p1 = g_pos[t * 2 + 1];
    out[idx] = g_pairout[(size_t)p0 * H_DIM + h] + g_pairout[(size_t)p1 * H_DIM + h];
}

// ---------------- launcher ----------------------------------------------------
extern "C" void kernel_launch(void* const* d_in, const int* in_sizes, int n_in,
                              void* d_out, int out_size) {
    const float* x  = (const float*)d_in[0];
    const float* gw = (const float*)d_in[1];
    const float* wg = (const float*)d_in[2];
    const float* wu = (const float*)d_in[3];
    const float* wd = (const float*)d_in[4];
    float* out = (float*)d_out;

    static int attr_set = 0;
    if (!attr_set) {
        cudaFuncSetAttribute(ffn1_kernel, cudaFuncAttributeMaxDynamicSharedMemorySize,
                             4 * F1_STG * 8);
        cudaFuncSetAttribute(ffn2_kernel, cudaFuncAttributeMaxDynamicSharedMemorySize,
                             4 * F2_STG * 8);
        attr_set = 1;
    }

    zero_kernel<<<1, 32>>>();
    router_kernel<<<T_TOK, 256>>>(x, gw);
    int write_aux = (out_size > T_TOK * H_DIM) ? 1 : 0;
    finalize_router<<<1, 1>>>(out + (size_t)T_TOK * H_DIM, write_aux);
    scatter_kernel<<<(T_TOK + 255) / 256, 256>>>();

    uint2 *xs, *wgs, *wus, *wds;
    cudaGetSymbolAddress((void**)&xs,  g_xs);
    cudaGetSymbolAddress((void**)&wgs, g_wgs);
    cudaGetSymbolAddress((void**)&wus, g_wus);
    cudaGetSymbolAddress((void**)&wds, g_wds);

    split_x_kernel<<<2048, 256>>>(x, xs, (long)T_TOK * H_DIM / 4);
    split_w_kernel<<<8192, 256>>>(wg, wgs, (long)E_EXP * HP, I_DIM);
    split_w_kernel<<<8192, 256>>>(wu, wus, (long)E_EXP * HP, I_DIM);
    split_w_kernel<<<8192, 256>>>(wd, wds, (long)E_EXP * IP, H_DIM);

    dim3 g1(T_TOK / 128, I_DIM / 64, E_EXP);
    ffn1_kernel<<<g1, 256, 4 * F1_STG * 8>>>();
    dim3 g2(T_TOK / 128, H_DIM / 128, E_EXP);
    ffn2_kernel<<<g2, 256, 4 * F2_STG * 8>>>();

    combine_kernel<<<(T_TOK * H_DIM + 255) / 256, 256>>>(out);
}

// round 14
// speedup vs baseline: 1.0004x; 1.0004x over previous
#include <cuda_runtime.h>
#include <cuda_bf16.h>
#include <math.h>

// Problem constants
#define T_TOK 4096
#define H_DIM 1024
#define I_DIM 4096
#define E_EXP 8
#define K_TOP 2
#define P_PAIR (T_TOK * K_TOP)
#define HP (H_DIM / 2)   // k-pairs along H
#define IP (I_DIM / 2)   // k-pairs along I

// ---------------- scratch (static device globals; no runtime alloc) ----------
// bf16x3 split storage: one uint2 per k-PAIR of fp32 elements:
//   .x = bf16x2{hi(k_even), hi(k_odd)}
//   .y = bf16x2{lo(k_even), lo(k_odd)}   (residuals)
__device__ uint2 g_xs [(size_t)T_TOK * HP];
__device__ uint2 g_wgs[(size_t)E_EXP * HP * I_DIM];
__device__ uint2 g_wus[(size_t)E_EXP * HP * I_DIM];
__device__ uint2 g_wds[(size_t)E_EXP * IP * H_DIM];
__device__ uint2 g_hdns[(size_t)P_PAIR * IP];
__device__ float g_pairout[(size_t)P_PAIR * H_DIM];
__device__ int   g_perm[P_PAIR];
__device__ float g_pairw[P_PAIR];
__device__ int   g_pos[P_PAIR];
__device__ int   g_tki[T_TOK * K_TOP];
__device__ float g_tkw[T_TOK * K_TOP];
__device__ int   g_counts[E_EXP];
__device__ int   g_offsets[E_EXP];
__device__ int   g_cursor[E_EXP];
__device__ float g_load[E_EXP];

// ---------------- bf16 split + mma helpers -----------------------------------
__device__ __forceinline__ uint2 split_pair(float e0, float e1) {
    __nv_bfloat16 h0 = __float2bfloat16_rn(e0);
    __nv_bfloat16 h1 = __float2bfloat16_rn(e1);
    float r0 = e0 - __bfloat162float(h0);
    float r1 = e1 - __bfloat162float(h1);
    __nv_bfloat16 l0 = __float2bfloat16_rn(r0);
    __nv_bfloat16 l1 = __float2bfloat16_rn(r1);
    uint2 o;
    o.x = (unsigned)__bfloat16_as_ushort(h0) | ((unsigned)__bfloat16_as_ushort(h1) << 16);
    o.y = (unsigned)__bfloat16_as_ushort(l0) | ((unsigned)__bfloat16_as_ushort(l1) << 16);
    return o;
}
__device__ __forceinline__ void mma16(float* c, unsigned a0, unsigned a1,
                                      unsigned a2, unsigned a3,
                                      unsigned b0, unsigned b1) {
    asm volatile(
        "mma.sync.aligned.m16n8k16.row.col.f32.bf16.bf16.f32 "
        "{%0,%1,%2,%3}, {%4,%5,%6,%7}, {%8,%9}, {%0,%1,%2,%3};"
        : "+f"(c[0]), "+f"(c[1]), "+f"(c[2]), "+f"(c[3])
        : "r"(a0), "r"(a1), "r"(a2), "r"(a3), "r"(b0), "r"(b1));
}
__device__ __forceinline__ void mma3(float* c, const uint2 a[4], uint2 b0, uint2 b1) {
    mma16(c, a[0].x, a[1].x, a[2].x, a[3].x, b0.x, b1.x);
    mma16(c, a[0].y, a[1].y, a[2].y, a[3].y, b0.x, b1.x);
    mma16(c, a[0].x, a[1].x, a[2].x, a[3].x, b0.y, b1.y);
}
__device__ __forceinline__ void cp16(unsigned dst, const void* src) {
    asm volatile("cp.async.cg.shared.global [%0], [%1], 16;" :: "r"(dst), "l"(src));
}
#define CP_COMMIT() asm volatile("cp.async.commit_group;")
#define CP_WAIT(n)  asm volatile("cp.async.wait_group %0;" :: "n"(n))

// ---------------- small kernels ----------------------------------------------
__global__ void zero_kernel() {
    int i = threadIdx.x;
    if (i < E_EXP) { g_counts[i] = 0; g_load[i] = 0.f; }
}

__global__ void router_kernel(const float* __restrict__ x,
                              const float* __restrict__ gw) {
    int t = blockIdx.x;
    int w = threadIdx.x >> 5, lane = threadIdx.x & 31;
    __shared__ float logits[E_EXP];
    const float* xr = x + (size_t)t * H_DIM;
    float s = 0.f;
    for (int h = lane; h < H_DIM; h += 32)
        s += xr[h] * gw[h * E_EXP + w];
    #pragma unroll
    for (int o = 16; o; o >>= 1) s += __shfl_xor_sync(0xffffffffu, s, o);
    if (lane == 0) logits[w] = s;
    __syncthreads();
    if (threadIdx.x == 0) {
        float mx = logits[0];
        #pragma unroll
        for (int e = 1; e < E_EXP; e++) mx = fmaxf(mx, logits[e]);
        float p[E_EXP], den = 0.f;
        #pragma unroll
        for (int e = 0; e < E_EXP; e++) { p[e] = expf(logits[e] - mx); den += p[e]; }
        #pragma unroll
        for (int e = 0; e < E_EXP; e++) p[e] /= den;
        int i0 = 0;
        #pragma unroll
        for (int e = 1; e < E_EXP; e++) if (p[e] > p[i0]) i0 = e;
        int i1 = -1;
        #pragma unroll
        for (int e = 0; e < E_EXP; e++) {
            if (e == i0) continue;
            if (i1 < 0 || p[e] > p[i1]) i1 = e;
        }
        float w0 = p[i0], w1 = p[i1], sm = w0 + w1;
        g_tki[t * 2 + 0] = i0; g_tki[t * 2 + 1] = i1;
        g_tkw[t * 2 + 0] = w0 / sm; g_tkw[t * 2 + 1] = w1 / sm;
        atomicAdd(&g_counts[i0], 1); atomicAdd(&g_counts[i1], 1);
        atomicAdd(&g_load[i0], w0);  atomicAdd(&g_load[i1], w1);
    }
}

__global__ void finalize_router(float* out_aux, int write_aux) {
    if (threadIdx.x == 0) {
        int off = 0;
        for (int e = 0; e < E_EXP; e++) {
            g_offsets[e] = off; g_cursor[e] = off; off += g_counts[e];
        }
        if (write_aux) {
            float aux = 0.f;
            for (int e = 0; e < E_EXP; e++) {
                float Pe = g_load[e] / (float)T_TOK;
                float Pt = (float)g_counts[e] / (float)(T_TOK * K_TOP);
                aux += Pe * Pt;
            }
            *out_aux = aux * (float)E_EXP * 0.001f;
        }
    }
}

__global__ void scatter_kernel() {
    int t = blockIdx.x * blockDim.x + threadIdx.x;
    if (t >= T_TOK) return;
    #pragma unroll
    for (int k = 0; k < K_TOP; k++) {
        int e = g_tki[t * 2 + k];
        int p = atomicAdd(&g_cursor[e], 1);
        g_perm[p] = t;
        g_pairw[p] = g_tkw[t * 2 + k];
        g_pos[t * 2 + k] = p;
    }
}

// ---------------- preprocessing ----------------------------------------------
__global__ void split_x_kernel(const float* __restrict__ src,
                               uint2* __restrict__ dst, long n4) {
    long stride = (long)gridDim.x * blockDim.x;
    for (long i = (long)blockIdx.x * blockDim.x + threadIdx.x; i < n4; i += stride) {
        float4 v = ((const float4*)src)[i];
        uint2 p0 = split_pair(v.x, v.y);
        uint2 p1 = split_pair(v.z, v.w);
        uint4 o; o.x = p0.x; o.y = p0.y; o.z = p1.x; o.w = p1.y;
        ((uint4*)dst)[i] = o;
    }
}

__global__ void split_w_kernel(const float* __restrict__ src,
                               uint2* __restrict__ dst, long Rp, int C) {
    long total = Rp * (long)(C / 4);
    long stride = (long)gridDim.x * blockDim.x;
    int c4 = C / 4;
    for (long i = (long)blockIdx.x * blockDim.x + threadIdx.x; i < total; i += stride) {
        long kp = i / c4;
        int  n4 = (int)(i % c4) * 4;
        const float* r0 = src + (size_t)(2 * kp) * C + n4;
        float4 a = *(const float4*)r0;
        float4 b = *(const float4*)(r0 + C);
        uint2 p0 = split_pair(a.x, b.x);
        uint2 p1 = split_pair(a.y, b.y);
        uint2 p2 = split_pair(a.z, b.z);
        uint2 p3 = split_pair(a.w, b.w);
        uint2* dp = dst + (size_t)kp * C + n4;
        uint4 o0; o0.x = p0.x; o0.y = p0.y; o0.z = p1.x; o0.w = p1.y;
        uint4 o1; o1.x = p2.x; o1.y = p2.y; o1.z = p3.x; o1.w = p3.y;
        ((uint4*)dp)[0] = o0;
        ((uint4*)dp)[1] = o1;
    }
}

// ---------------- GEMM1: hdn = silu(X@wg[e]) * (X@wu[e]) ---------------------
// Block 128M x 64N, 8 warps 4mx2n, warp tile 32x32 for G and U.
// 3-stage cp.async ring (k16/stage), 2 CTAs/SM target.
#define F1_AS 1536          // 128*12 uint2
#define F1_BS 544           // 8*68 uint2
#define F1_STG (F1_AS + 2 * F1_BS)   // 2624 uint2 = 20992 B per stage
__global__ void __launch_bounds__(256, 2) ffn1_kernel() {
    extern __shared__ __align__(16) uint2 dsm[];
    __shared__ int perm_s[128];

    const int e = blockIdx.z;
    const int cnt = g_counts[e];
    const int m0 = blockIdx.x * 128;
    if (m0 >= cnt) return;
    const int beg = g_offsets[e];
    const int n0 = blockIdx.y * 64;
    const int tid = threadIdx.x;

    if (tid < 128) {
        int r = m0 + tid;
        perm_s[tid] = g_perm[beg + (r < cnt ? r : cnt - 1)];
    }
    __syncthreads();

    const int ar  = tid >> 1;
    const int apb = (tid & 1) * 4;
    const uint2* axr = g_xs + (size_t)perm_s[ar] * HP + apb;
    const int bkp = tid >> 5;
    const int bn  = (tid & 31) * 2;
    const size_t eoffB = (size_t)e * HP * I_DIM;
    const uint2* bgp = g_wgs + eoffB + (size_t)bkp * I_DIM + n0 + bn;
    const uint2* bup = g_wus + eoffB + (size_t)bkp * I_DIM + n0 + bn;

    const unsigned sm0 = (unsigned)__cvta_generic_to_shared(dsm);
    const unsigned a_sm = sm0 + (unsigned)(ar * 12 + apb) * 8;
    const unsigned g_sm = sm0 + (unsigned)(F1_AS + bkp * 68 + bn) * 8;
    const unsigned u_sm = sm0 + (unsigned)(F1_AS + F1_BS + bkp * 68 + bn) * 8;
    const unsigned STGB = F1_STG * 8;

    const int w = tid >> 5, lane = tid & 31;
    const int wm = (w >> 1) * 32, wn = (w & 1) * 32;
    const int fr = lane >> 2, fc = lane & 3;

    float accG[2][4][4] = {}, accU[2][4][4] = {};

    const int KT = HP / 8;  // 64
    // prologue: fill stages 0..1
    #pragma unroll
    for (int s = 0; s < 2; s++) {
        const uint2* a2 = axr + s * 8;
        cp16(a_sm + s * STGB, a2); cp16(a_sm + s * STGB + 16, a2 + 2);
        cp16(g_sm + s * STGB, bgp + (size_t)s * 8 * I_DIM);
        cp16(u_sm + s * STGB, bup + (size_t)s * 8 * I_DIM);
        CP_COMMIT();
    }

    for (int kt = 0; kt < KT; kt++) {
        CP_WAIT(1);          // stage kt landed (kt+1 may still be in flight)
        __syncthreads();     // visible to all; all warps done with stage kt-1
        const int pf = kt + 2;
        if (pf < KT) {
            const unsigned so = (unsigned)(pf % 3) * STGB;
            const uint2* a2 = axr + pf * 8;
            cp16(a_sm + so, a2); cp16(a_sm + so + 16, a2 + 2);
            cp16(g_sm + so, bgp + (size_t)pf * 8 * I_DIM);
            cp16(u_sm + so, bup + (size_t)pf * 8 * I_DIM);
        }
        CP_COMMIT();         // keep group count aligned (empty near tail)

        const uint2* A  = dsm + (kt % 3) * F1_STG;
        const uint2* BG = A + F1_AS;
        const uint2* BU = BG + F1_BS;
        uint2 a[2][4];
        #pragma unroll
        for (int mi = 0; mi < 2; mi++) {
            int mr = wm + mi * 16 + fr;
            a[mi][0] = A[mr * 12 + fc];
            a[mi][1] = A[(mr + 8) * 12 + fc];
            a[mi][2] = A[mr * 12 + fc + 4];
            a[mi][3] = A[(mr + 8) * 12 + fc + 4];
        }
        #pragma unroll
        for (int nj = 0; nj < 4; nj++) {
            int nb = wn + nj * 8 + fr;
            uint2 b0 = BG[fc * 68 + nb], b1 = BG[(fc + 4) * 68 + nb];
            mma3(accG[0][nj], a[0], b0, b1);
            mma3(accG[1][nj], a[1], b0, b1);
            b0 = BU[fc * 68 + nb]; b1 = BU[(fc + 4) * 68 + nb];
            mma3(accU[0][nj], a[0], b0, b1);
            mma3(accU[1][nj], a[1], b0, b1);
        }
    }

    #pragma unroll
    for (int mi = 0; mi < 2; mi++) {
        #pragma unroll
        for (int nj = 0; nj < 4; nj++) {
            int row = m0 + wm + mi * 16 + fr;
            int pr  = (n0 + wn + nj * 8 + 2 * fc) >> 1;
            if (row < cnt) {
                float g0 = accG[mi][nj][0], g1 = accG[mi][nj][1];
                float u0 = accU[mi][nj][0], u1 = accU[mi][nj][1];
                float h0 = g0 / (1.f + expf(-g0)) * u0;
                float h1 = g1 / (1.f + expf(-g1)) * u1;
                g_hdns[(size_t)(beg + row) * IP + pr] = split_pair(h0, h1);
            }
            if (row + 8 < cnt) {
                float g0 = accG[mi][nj][2], g1 = accG[mi][nj][3];
                float u0 = accU[mi][nj][2], u1 = accU[mi][nj][3];
                float h0 = g0 / (1.f + expf(-g0)) * u0;
                float h1 = g1 / (1.f + expf(-g1)) * u1;
                g_hdns[(size_t)(beg + row + 8) * IP + pr] = split_pair(h0, h1);
            }
        }
    }
}

// ---------------- GEMM2: pairout = (hdn @ wd[e]) * pairw ---------------------
// Block 128M x 128N, 8 warps 4mx2n, warp tile 32x64. 3-stage ring, 2 CTAs/SM.
#define F2_AS 1536
#define F2_BS 1056          // 8*132 uint2
#define F2_STG (F2_AS + F2_BS)    // 2592 uint2 = 20736 B
__global__ void __launch_bounds__(256, 2) ffn2_kernel() {
    extern __shared__ __align__(16) uint2 dsm2[];

    const int e = blockIdx.z;
    const int cnt = g_counts[e];
    const int m0 = blockIdx.x * 128;
    if (m0 >= cnt) return;
    const int beg = g_offsets[e];
    const int n0 = blockIdx.y * 128;
    const int tid = threadIdx.x;

    const int ar  = tid >> 1;
    const int apb = (tid & 1) * 4;
    int rr = m0 + ar; if (rr >= cnt) rr = cnt - 1;
    const uint2* axr = g_hdns + (size_t)(beg + rr) * IP + apb;
    const int bkp = tid >> 5;
    const int bn4 = (tid & 31) * 4;
    const uint2* bp = g_wds + ((size_t)e * IP + bkp) * H_DIM + n0 + bn4;

    const unsigned sm0 = (unsigned)__cvta_generic_to_shared(dsm2);
    const unsigned a_sm = sm0 + (unsigned)(ar * 12 + apb) * 8;
    const unsigned b_sm = sm0 + (unsigned)(F2_AS + bkp * 132 + bn4) * 8;
    const unsigned STGB = F2_STG * 8;

    const int w = tid >> 5, lane = tid & 31;
    const int wm = (w >> 1) * 32, wn = (w & 1) * 64;
    const int fr = lane >> 2, fc = lane & 3;

    float acc[2][8][4] = {};

    const int KT = IP / 8;  // 256
    #pragma unroll
    for (int s = 0; s < 2; s++) {
        const uint2* a2 = axr + s * 8;
        const uint2* b2 = bp + (size_t)s * 8 * H_DIM;
        cp16(a_sm + s * STGB, a2); cp16(a_sm + s * STGB + 16, a2 + 2);
        cp16(b_sm + s * STGB, b2); cp16(b_sm + s * STGB + 16, b2 + 2);
        CP_COMMIT();
    }

    for (int kt = 0; kt < KT; kt++) {
        CP_WAIT(1);
        __syncthreads();
        const int pf = kt + 2;
        if (pf < KT) {
            const unsigned so = (unsigned)(pf % 3) * STGB;
            const uint2* a2 = axr + pf * 8;
            const uint2* b2 = bp + (size_t)pf * 8 * H_DIM;
            cp16(a_sm + so, a2); cp16(a_sm + so + 16, a2 + 2);
            cp16(b_sm + so, b2); cp16(b_sm + so + 16, b2 + 2);
        }
        CP_COMMIT();

        const uint2* A = dsm2 + (kt % 3) * F2_STG;
        const uint2* B = A + F2_AS;
        uint2 a[2][4];
        #pragma unroll
        for (int mi = 0; mi < 2; mi++) {
            int mr = wm + mi * 16 + fr;
            a[mi][0] = A[mr * 12 + fc];
            a[mi][1] = A[(mr + 8) * 12 + fc];
            a[mi][2] = A[mr * 12 + fc + 4];
            a[mi][3] = A[(mr + 8) * 12 + fc + 4];
        }
        #pragma unroll
        for (int nj = 0; nj < 8; nj++) {
            int nb = wn + nj * 8 + fr;
            uint2 b0 = B[fc * 132 + nb], b1 = B[(fc + 4) * 132 + nb];
            mma3(acc[0][nj], a[0], b0, b1);
            mma3(acc[1][nj], a[1], b0, b1);
        }
    }

    #pragma unroll
    for (int mi = 0; mi < 2; mi++) {
        int row = m0 + wm + mi * 16 + fr;
        float pw0 = (row < cnt)     ? g_pairw[beg + row]     : 0.f;
        float pw8 = (row + 8 < cnt) ? g_pairw[beg + row + 8] : 0.f;
        #pragma unroll
        for (int nj = 0; nj < 8; nj++) {
            int col = n0 + wn + nj * 8 + 2 * fc;
            if (row < cnt) {
                float2 v = { acc[mi][nj][0] * pw0, acc[mi][nj][1] * pw0 };
                *(float2*)&g_pairout[(size_t)(beg + row) * H_DIM + col] = v;
            }
            if (row + 8 < cnt) {
                float2 v = { acc[mi][nj][2] * pw8, acc[mi][nj][3] * pw8 };
                *(float2*)&g_pairout[(size_t)(beg + row + 8) * H_DIM + col] = v;
            }
        }
    }
}

// ---------------- combine ------------------------------------------------------
__global__ void combine_kernel(float* __restrict__ out) {
    int idx = blockIdx.x * blockDim.x + threadIdx.x;
    if (idx >= T_TOK * H_DIM) return;
    int t = idx >> 10;
    int h = idx & (H_DIM - 1);
    int p0 = g_pos[t * 2 + 0], p1 = g_pos[t * 2 + 1];
    out[idx] = g_pairout[(size_t)p0 * H_DIM + h] + g_pairout[(size_t)p1 * H_DIM + h];
}

// ---------------- launcher ----------------------------------------------------
extern "C" void kernel_launch(void* const* d_in, const int* in_sizes, int n_in,
                              void* d_out, int out_size) {
    const float* x  = (const float*)d_in[0];
    const float* gw = (const float*)d_in[1];
    const float* wg = (const float*)d_in[2];
    const float* wu = (const float*)d_in[3];
    const float* wd = (const float*)d_in[4];
    float* out = (float*)d_out;

    static int attr_set = 0;
    if (!attr_set) {
        cudaFuncSetAttribute(ffn1_kernel, cudaFuncAttributeMaxDynamicSharedMemorySize,
                             3 * F1_STG * 8);
        cudaFuncSetAttribute(ffn2_kernel, cudaFuncAttributeMaxDynamicSharedMemorySize,
                             3 * F2_STG * 8);
        attr_set = 1;
    }

    zero_kernel<<<1, 32>>>();
    router_kernel<<<T_TOK, 256>>>(x, gw);
    int write_aux = (out_size > T_TOK * H_DIM) ? 1 : 0;
    finalize_router<<<1, 1>>>(out + (size_t)T_TOK * H_DIM, write_aux);
    scatter_kernel<<<(T_TOK + 255) / 256, 256>>>();

    uint2 *xs, *wgs, *wus, *wds;
    cudaGetSymbolAddress((void**)&xs,  g_xs);
    cudaGetSymbolAddress((void**)&wgs, g_wgs);
    cudaGetSymbolAddress((void**)&wus, g_wus);
    cudaGetSymbolAddress((void**)&wds, g_wds);

    split_x_kernel<<<2048, 256>>>(x, xs, (long)T_TOK * H_DIM / 4);
    split_w_kernel<<<8192, 256>>>(wg, wgs, (long)E_EXP * HP, I_DIM);
    split_w_kernel<<<8192, 256>>>(wu, wus, (long)E_EXP * HP, I_DIM);
    split_w_kernel<<<8192, 256>>>(wd, wds, (long)E_EXP * IP, H_DIM);

    dim3 g1(T_TOK / 128, I_DIM / 64, E_EXP);
    ffn1_kernel<<<g1, 256, 3 * F1_STG * 8>>>();
    dim3 g2(T_TOK / 128, H_DIM / 128, E_EXP);
    ffn2_kernel<<<g2, 256, 3 * F2_STG * 8>>>();

    combine_kernel<<<(T_TOK * H_DIM + 255) / 256, 256>>>(out);
}

// round 15
// speedup vs baseline: 1.0010x; 1.0007x over previous
#include <cuda_runtime.h>
#include <cuda_bf16.h>
#include <math.h>

// Problem constants
#define T_TOK 4096
#define H_DIM 1024
#define I_DIM 4096
#define E_EXP 8
#define K_TOP 2
#define P_PAIR (T_TOK * K_TOP)
#define HP (H_DIM / 2)   // k-pairs along H
#define IP (I_DIM / 2)   // k-pairs along I

// ---------------- scratch (static device globals; no runtime alloc) ----------
// bf16x3 split storage: one uint2 per k-PAIR of fp32 elements:
//   .x = bf16x2{hi(k_even), hi(k_odd)}
//   .y = bf16x2{lo(k_even), lo(k_odd)}   (residuals)
__device__ uint2 g_xs [(size_t)T_TOK * HP];
__device__ uint2 g_wgs[(size_t)E_EXP * HP * I_DIM];
__device__ uint2 g_wus[(size_t)E_EXP * HP * I_DIM];
__device__ uint2 g_wds[(size_t)E_EXP * IP * H_DIM];
__device__ uint2 g_hdns[(size_t)P_PAIR * IP];
__device__ float g_pairout[(size_t)P_PAIR * H_DIM];
__device__ int   g_perm[P_PAIR];
__device__ float g_pairw[P_PAIR];
__device__ int   g_pos[P_PAIR];
__device__ int   g_tki[T_TOK * K_TOP];
__device__ float g_tkw[T_TOK * K_TOP];
__device__ int   g_counts[E_EXP];
__device__ int   g_offsets[E_EXP];
__device__ int   g_cursor[E_EXP];
__device__ float g_load[E_EXP];

// ---------------- bf16 split + mma helpers -----------------------------------
__device__ __forceinline__ uint2 split_pair(float e0, float e1) {
    __nv_bfloat16 h0 = __float2bfloat16_rn(e0);
    __nv_bfloat16 h1 = __float2bfloat16_rn(e1);
    float r0 = e0 - __bfloat162float(h0);
    float r1 = e1 - __bfloat162float(h1);
    __nv_bfloat16 l0 = __float2bfloat16_rn(r0);
    __nv_bfloat16 l1 = __float2bfloat16_rn(r1);
    uint2 o;
    o.x = (unsigned)__bfloat16_as_ushort(h0) | ((unsigned)__bfloat16_as_ushort(h1) << 16);
    o.y = (unsigned)__bfloat16_as_ushort(l0) | ((unsigned)__bfloat16_as_ushort(l1) << 16);
    return o;
}
__device__ __forceinline__ void mma16(float* c, unsigned a0, unsigned a1,
                                      unsigned a2, unsigned a3,
                                      unsigned b0, unsigned b1) {
    asm volatile(
        "mma.sync.aligned.m16n8k16.row.col.f32.bf16.bf16.f32 "
        "{%0,%1,%2,%3}, {%4,%5,%6,%7}, {%8,%9}, {%0,%1,%2,%3};"
        : "+f"(c[0]), "+f"(c[1]), "+f"(c[2]), "+f"(c[3])
        : "r"(a0), "r"(a1), "r"(a2), "r"(a3), "r"(b0), "r"(b1));
}
__device__ __forceinline__ void mma3(float* c, const uint2 a[4], uint2 b0, uint2 b1) {
    mma16(c, a[0].x, a[1].x, a[2].x, a[3].x, b0.x, b1.x);
    mma16(c, a[0].y, a[1].y, a[2].y, a[3].y, b0.x, b1.x);
    mma16(c, a[0].x, a[1].x, a[2].x, a[3].x, b0.y, b1.y);
}
__device__ __forceinline__ void cp16(unsigned dst, const void* src) {
    asm volatile("cp.async.cg.shared.global [%0], [%1], 16;" :: "r"(dst), "l"(src));
}
#define CP_COMMIT() asm volatile("cp.async.commit_group;")
#define CP_WAIT(n)  asm volatile("cp.async.wait_group %0;" :: "n"(n))

// ---------------- small kernels ----------------------------------------------
__global__ void zero_kernel() {
    int i = threadIdx.x;
    if (i < E_EXP) { g_counts[i] = 0; g_load[i] = 0.f; }
}

__global__ void router_kernel(const float* __restrict__ x,
                              const float* __restrict__ gw) {
    int t = blockIdx.x;
    int w = threadIdx.x >> 5, lane = threadIdx.x & 31;
    __shared__ float logits[E_EXP];
    const float* xr = x + (size_t)t * H_DIM;
    float s = 0.f;
    for (int h = lane; h < H_DIM; h += 32)
        s += xr[h] * gw[h * E_EXP + w];
    #pragma unroll
    for (int o = 16; o; o >>= 1) s += __shfl_xor_sync(0xffffffffu, s, o);
    if (lane == 0) logits[w] = s;
    __syncthreads();
    if (threadIdx.x == 0) {
        float mx = logits[0];
        #pragma unroll
        for (int e = 1; e < E_EXP; e++) mx = fmaxf(mx, logits[e]);
        float p[E_EXP], den = 0.f;
        #pragma unroll
        for (int e = 0; e < E_EXP; e++) { p[e] = expf(logits[e] - mx); den += p[e]; }
        #pragma unroll
        for (int e = 0; e < E_EXP; e++) p[e] /= den;
        int i0 = 0;
        #pragma unroll
        for (int e = 1; e < E_EXP; e++) if (p[e] > p[i0]) i0 = e;
        int i1 = -1;
        #pragma unroll
        for (int e = 0; e < E_EXP; e++) {
            if (e == i0) continue;
            if (i1 < 0 || p[e] > p[i1]) i1 = e;
        }
        float w0 = p[i0], w1 = p[i1], sm = w0 + w1;
        g_tki[t * 2 + 0] = i0; g_tki[t * 2 + 1] = i1;
        g_tkw[t * 2 + 0] = w0 / sm; g_tkw[t * 2 + 1] = w1 / sm;
        atomicAdd(&g_counts[i0], 1); atomicAdd(&g_counts[i1], 1);
        atomicAdd(&g_load[i0], w0);  atomicAdd(&g_load[i1], w1);
    }
}

__global__ void finalize_router(float* out_aux, int write_aux) {
    if (threadIdx.x == 0) {
        int off = 0;
        for (int e = 0; e < E_EXP; e++) {
            g_offsets[e] = off; g_cursor[e] = off; off += g_counts[e];
        }
        if (write_aux) {
            float aux = 0.f;
            for (int e = 0; e < E_EXP; e++) {
                float Pe = g_load[e] / (float)T_TOK;
                float Pt = (float)g_counts[e] / (float)(T_TOK * K_TOP);
                aux += Pe * Pt;
            }
            *out_aux = aux * (float)E_EXP * 0.001f;
        }
    }
}

__global__ void scatter_kernel() {
    int t = blockIdx.x * blockDim.x + threadIdx.x;
    if (t >= T_TOK) return;
    #pragma unroll
    for (int k = 0; k < K_TOP; k++) {
        int e = g_tki[t * 2 + k];
        int p = atomicAdd(&g_cursor[e], 1);
        g_perm[p] = t;
        g_pairw[p] = g_tkw[t * 2 + k];
        g_pos[t * 2 + k] = p;
    }
}

// ---------------- preprocessing ----------------------------------------------
__global__ void split_x_kernel(const float* __restrict__ src,
                               uint2* __restrict__ dst, long n4) {
    long stride = (long)gridDim.x * blockDim.x;
    for (long i = (long)blockIdx.x * blockDim.x + threadIdx.x; i < n4; i += stride) {
        float4 v = ((const float4*)src)[i];
        uint2 p0 = split_pair(v.x, v.y);
        uint2 p1 = split_pair(v.z, v.w);
        uint4 o; o.x = p0.x; o.y = p0.y; o.z = p1.x; o.w = p1.y;
        ((uint4*)dst)[i] = o;
    }
}

__global__ void split_w_kernel(const float* __restrict__ src,
                               uint2* __restrict__ dst, long Rp, int C) {
    long total = Rp * (long)(C / 4);
    long stride = (long)gridDim.x * blockDim.x;
    int c4 = C / 4;
    for (long i = (long)blockIdx.x * blockDim.x + threadIdx.x; i < total; i += stride) {
        long kp = i / c4;
        int  n4 = (int)(i % c4) * 4;
        const float* r0 = src + (size_t)(2 * kp) * C + n4;
        float4 a = *(const float4*)r0;
        float4 b = *(const float4*)(r0 + C);
        uint2 p0 = split_pair(a.x, b.x);
        uint2 p1 = split_pair(a.y, b.y);
        uint2 p2 = split_pair(a.z, b.z);
        uint2 p3 = split_pair(a.w, b.w);
        uint2* dp = dst + (size_t)kp * C + n4;
        uint4 o0; o0.x = p0.x; o0.y = p0.y; o0.z = p1.x; o0.w = p1.y;
        uint4 o1; o1.x = p2.x; o1.y = p2.y; o1.z = p3.x; o1.w = p3.y;
        ((uint4*)dp)[0] = o0;
        ((uint4*)dp)[1] = o1;
    }
}

// ---------------- GEMM1: hdn = silu(X@wg[e]) * (X@wu[e]) ---------------------
// Block 128M x 64N, 8 warps 4mx2n, warp tile 32x32 for G and U.
// 3-stage cp.async ring (k16/stage), 2 CTAs/SM target.
#define F1_AS 1536          // 128*12 uint2
#define F1_BS 544           // 8*68 uint2
#define F1_STG (F1_AS + 2 * F1_BS)   // 2624 uint2 = 20992 B per stage
__global__ void __launch_bounds__(256, 2) ffn1_kernel() {
    extern __shared__ __align__(16) uint2 dsm[];
    __shared__ int perm_s[128];

    const int e = blockIdx.z;
    const int cnt = g_counts[e];
    const int m0 = blockIdx.x * 128;
    if (m0 >= cnt) return;
    const int beg = g_offsets[e];
    const int n0 = blockIdx.y * 64;
    const int tid = threadIdx.x;

    if (tid < 128) {
        int r = m0 + tid;
        perm_s[tid] = g_perm[beg + (r < cnt ? r : cnt - 1)];
    }
    __syncthreads();

    const int ar  = tid >> 1;
    const int apb = (tid & 1) * 4;
    const uint2* axr = g_xs + (size_t)perm_s[ar] * HP + apb;
    const int bkp = tid >> 5;
    const int bn  = (tid & 31) * 2;
    const size_t eoffB = (size_t)e * HP * I_DIM;
    const uint2* bgp = g_wgs + eoffB + (size_t)bkp * I_DIM + n0 + bn;
    const uint2* bup = g_wus + eoffB + (size_t)bkp * I_DIM + n0 + bn;

    const unsigned sm0 = (unsigned)__cvta_generic_to_shared(dsm);
    const unsigned a_sm = sm0 + (unsigned)(ar * 12 + apb) * 8;
    const unsigned g_sm = sm0 + (unsigned)(F1_AS + bkp * 68 + bn) * 8;
    const unsigned u_sm = sm0 + (unsigned)(F1_AS + F1_BS + bkp * 68 + bn) * 8;
    const unsigned STGB = F1_STG * 8;

    const int w = tid >> 5, lane = tid & 31;
    const int wm = (w >> 1) * 32, wn = (w & 1) * 32;
    const int fr = lane >> 2, fc = lane & 3;

    float accG[2][4][4] = {}, accU[2][4][4] = {};

    const int KT = HP / 8;  // 64
    // prologue: fill stages 0..1
    #pragma unroll
    for (int s = 0; s < 2; s++) {
        const uint2* a2 = axr + s * 8;
        cp16(a_sm + s * STGB, a2); cp16(a_sm + s * STGB + 16, a2 + 2);
        cp16(g_sm + s * STGB, bgp + (size_t)s * 8 * I_DIM);
        cp16(u_sm + s * STGB, bup + (size_t)s * 8 * I_DIM);
        CP_COMMIT();
    }

    for (int kt = 0; kt < KT; kt++) {
        CP_WAIT(1);          // stage kt landed (kt+1 may still be in flight)
        __syncthreads();     // visible to all; all warps done with stage kt-1
        const int pf = kt + 2;
        if (pf < KT) {
            const unsigned so = (unsigned)(pf % 3) * STGB;
            const uint2* a2 = axr + pf * 8;
            cp16(a_sm + so, a2); cp16(a_sm + so + 16, a2 + 2);
            cp16(g_sm + so, bgp + (size_t)pf * 8 * I_DIM);
            cp16(u_sm + so, bup + (size_t)pf * 8 * I_DIM);
        }
        CP_COMMIT();         // keep group count aligned (empty near tail)

        const uint2* A  = dsm + (kt % 3) * F1_STG;
        const uint2* BG = A + F1_AS;
        const uint2* BU = BG + F1_BS;
        uint2 a[2][4];
        #pragma unroll
        for (int mi = 0; mi < 2; mi++) {
            int mr = wm + mi * 16 + fr;
            a[mi][0] = A[mr * 12 + fc];
            a[mi][1] = A[(mr + 8) * 12 + fc];
            a[mi][2] = A[mr * 12 + fc + 4];
            a[mi][3] = A[(mr + 8) * 12 + fc + 4];
        }
        #pragma unroll
        for (int nj = 0; nj < 4; nj++) {
            int nb = wn + nj * 8 + fr;
            uint2 b0 = BG[fc * 68 + nb], b1 = BG[(fc + 4) * 68 + nb];
            mma3(accG[0][nj], a[0], b0, b1);
            mma3(accG[1][nj], a[1], b0, b1);
            b0 = BU[fc * 68 + nb]; b1 = BU[(fc + 4) * 68 + nb];
            mma3(accU[0][nj], a[0], b0, b1);
            mma3(accU[1][nj], a[1], b0, b1);
        }
    }

    #pragma unroll
    for (int mi = 0; mi < 2; mi++) {
        #pragma unroll
        for (int nj = 0; nj < 4; nj++) {
            int row = m0 + wm + mi * 16 + fr;
            int pr  = (n0 + wn + nj * 8 + 2 * fc) >> 1;
            if (row < cnt) {
                float g0 = accG[mi][nj][0], g1 = accG[mi][nj][1];
                float u0 = accU[mi][nj][0], u1 = accU[mi][nj][1];
                float h0 = g0 / (1.f + expf(-g0)) * u0;
                float h1 = g1 / (1.f + expf(-g1)) * u1;
                g_hdns[(size_t)(beg + row) * IP + pr] = split_pair(h0, h1);
            }
            if (row + 8 < cnt) {
                float g0 = accG[mi][nj][2], g1 = accG[mi][nj][3];
                float u0 = accU[mi][nj][2], u1 = accU[mi][nj][3];
                float h0 = g0 / (1.f + expf(-g0)) * u0;
                float h1 = g1 / (1.f + expf(-g1)) * u1;
                g_hdns[(size_t)(beg + row + 8) * IP + pr] = split_pair(h0, h1);
            }
        }
    }
}

// ---------------- GEMM2: pairout = (hdn @ wd[e]) * pairw ---------------------
// Block 128M x 128N, 8 warps 4mx2n, warp tile 32x64. 3-stage ring, 2 CTAs/SM.
#define F2_AS 1536
#define F2_BS 1056          // 8*132 uint2
#define F2_STG (F2_AS + F2_BS)    // 2592 uint2 = 20736 B
__global__ void __launch_bounds__(256, 2) ffn2_kernel() {
    extern __shared__ __align__(16) uint2 dsm2[];

    const int e = blockIdx.z;
    const int cnt = g_counts[e];
    const int m0 = blockIdx.x * 128;
    if (m0 >= cnt) return;
    const int beg = g_offsets[e];
    const int n0 = blockIdx.y * 128;
    const int tid = threadIdx.x;

    const int ar  = tid >> 1;
    const int apb = (tid & 1) * 4;
    int rr = m0 + ar; if (rr >= cnt) rr = cnt - 1;
    const uint2* axr = g_hdns + (size_t)(beg + rr) * IP + apb;
    const int bkp = tid >> 5;
    const int bn4 = (tid & 31) * 4;
    const uint2* bp = g_wds + ((size_t)e * IP + bkp) * H_DIM + n0 + bn4;

    const unsigned sm0 = (unsigned)__cvta_generic_to_shared(dsm2);
    const unsigned a_sm = sm0 + (unsigned)(ar * 12 + apb) * 8;
    const unsigned b_sm = sm0 + (unsigned)(F2_AS + bkp * 132 + bn4) * 8;
    const unsigned STGB = F2_STG * 8;

    const int w = tid >> 5, lane = tid & 31;
    const int wm = (w >> 1) * 32, wn = (w & 1) * 64;
    const int fr = lane >> 2, fc = lane & 3;

    float acc[2][8][4] = {};

    const int KT = IP / 8;  // 256
    #pragma unroll
    for (int s = 0; s < 2; s++) {
        const uint2* a2 = axr + s * 8;
        const uint2* b2 = bp + (size_t)s * 8 * H_DIM;
        cp16(a_sm + s * STGB, a2); cp16(a_sm + s * STGB + 16, a2 + 2);
        cp16(b_sm + s * STGB, b2); cp16(b_sm + s * STGB + 16, b2 + 2);
        CP_COMMIT();
    }

    for (int kt = 0; kt < KT; kt++) {
        CP_WAIT(1);
        __syncthreads();
        const int pf = kt + 2;
        if (pf < KT) {
            const unsigned so = (unsigned)(pf % 3) * STGB;
            const uint2* a2 = axr + pf * 8;
            const uint2* b2 = bp + (size_t)pf * 8 * H_DIM;
            cp16(a_sm + so, a2); cp16(a_sm + so + 16, a2 + 2);
            cp16(b_sm + so, b2); cp16(b_sm + so + 16, b2 + 2);
        }
        CP_COMMIT();

        const uint2* A = dsm2 + (kt % 3) * F2_STG;
        const uint2* B = A + F2_AS;
        uint2 a[2][4];
        #pragma unroll
        for (int mi = 0; mi < 2; mi++) {
            int mr = wm + mi * 16 + fr;
            a[mi][0] = A[mr * 12 + fc];
            a[mi][1] = A[(mr + 8) * 12 + fc];
            a[mi][2] = A[mr * 12 + fc + 4];
            a[mi][3] = A[(mr + 8) * 12 + fc + 4];
        }
        #pragma unroll
        for (int nj = 0; nj < 8; nj++) {
            int nb = wn + nj * 8 + fr;
            uint2 b0 = B[fc * 132 + nb], b1 = B[(fc + 4) * 132 + nb];
            mma3(acc[0][nj], a[0], b0, b1);
            mma3(acc[1][nj], a[1], b0, b1);
        }
    }

    #pragma unroll
    for (int mi = 0; mi < 2; mi++) {
        int row = m0 + wm + mi * 16 + fr;
        float pw0 = (row < cnt)     ? g_pairw[beg + row]     : 0.f;
        float pw8 = (row + 8 < cnt) ? g_pairw[beg + row + 8] : 0.f;
        #pragma unroll
        for (int nj = 0; nj < 8; nj++) {
            int col = n0 + wn + nj * 8 + 2 * fc;
            if (row < cnt) {
                float2 v = { acc[mi][nj][0] * pw0, acc[mi][nj][1] * pw0 };
                *(float2*)&g_pairout[(size_t)(beg + row) * H_DIM + col] = v;
            }
            if (row + 8 < cnt) {
                float2 v = { acc[mi][nj][2] * pw8, acc[mi][nj][3] * pw8 };
                *(float2*)&g_pairout[(size_t)(beg + row + 8) * H_DIM + col] = v;
            }
        }
    }
}

// ---------------- combine ------------------------------------------------------
__global__ void combine_kernel(float* __restrict__ out) {
    int idx = blockIdx.x * blockDim.x + threadIdx.x;
    if (idx >= T_TOK * H_DIM) return;
    int t = idx >> 10;
    int h = idx & (H_DIM - 1);
    int p0 = g_pos[t * 2 + 0], p1 = g_pos[t * 2 + 1];
    out[idx] = g_pairout[(size_t)p0 * H_DIM + h] + g_pairout[(size_t)p1 * H_DIM + h];
}

// ---------------- launcher ----------------------------------------------------
extern "C" void kernel_launch(void* const* d_in, const int* in_sizes, int n_in,
                              void* d_out, int out_size) {
    const float* x  = (const float*)d_in[0];
    const float* gw = (const float*)d_in[1];
    const float* wg = (const float*)d_in[2];
    const float* wu = (const float*)d_in[3];
    const float* wd = (const float*)d_in[4];
    float* out = (float*)d_out;

    static int attr_set = 0;
    if (!attr_set) {
        cudaFuncSetAttribute(ffn1_kernel, cudaFuncAttributeMaxDynamicSharedMemorySize,
                             3 * F1_STG * 8);
        cudaFuncSetAttribute(ffn2_kernel, cudaFuncAttributeMaxDynamicSharedMemorySize,
                             3 * F2_STG * 8);
        attr_set = 1;
    }

    zero_kernel<<<1, 32>>>();
    router_kernel<<<T_TOK, 256>>>(x, gw);
    int write_aux = (out_size > T_TOK * H_DIM) ? 1 : 0;
    finalize_router<<<1, 1>>>(out + (size_t)T_TOK * H_DIM, write_aux);
    scatter_kernel<<<(T_TOK + 255) / 256, 256>>>();

    uint2 *xs, *wgs, *wus, *wds;
    cudaGetSymbolAddress((void**)&xs,  g_xs);
    cudaGetSymbolAddress((void**)&wgs, g_wgs);
    cudaGetSymbolAddress((void**)&wus, g_wus);
    cudaGetSymbolAddress((void**)&wds, g_wds);

    split_x_kernel<<<2048, 256>>>(x, xs, (long)T_TOK * H_DIM / 4);
    split_w_kernel<<<8192, 256>>>(wg, wgs, (long)E_EXP * HP, I_DIM);
    split_w_kernel<<<8192, 256>>>(wu, wus, (long)E_EXP * HP, I_DIM);
    split_w_kernel<<<8192, 256>>>(wd, wds, (long)E_EXP * IP, H_DIM);

    dim3 g1(T_TOK / 128, I_DIM / 64, E_EXP);
    ffn1_kernel<<<g1, 256, 3 * F1_STG * 8>>>();
    dim3 g2(T_TOK / 128, H_DIM / 128, E_EXP);
    ffn2_kernel<<<g2, 256, 3 * F2_STG * 8>>>();

    combine_kernel<<<(T_TOK * H_DIM + 255) / 256, 256>>>(out);
}